// round 9
// baseline (speedup 1.0000x reference)
#include <cuda_runtime.h>
#include <cuda_bf16.h>

// Rows = 4194304, 16 fp32/row (64B), out = rows x 3 fp32 one-hot.
// selected = (f11 > 0.5) ? 0 : ((f4+f5 > f6+f7) ? 1 : 2)
//
// Fully-coalesced stream + warp-ballot predicate exchange (R6/R7 wins).
// R9: persistent grid-stride kernel, exactly ~1 wave (152 SMs x 8 CTAs).
// Removes per-wave latency ramps / wave-transition DRAM idle (DRAM was
// busy only 82% of kernel duration across R6-R8).
//
// Tile = 256 rows (8 warps x 32 rows). Lane l loads 4 contiguous float4
// (each LDG.128 = 512B warp-contiguous). Row r's predicates: lane 4r+1
// sees cols 4..7 (cmp = f4+f5 > f6+f7), lane 4r+2 sees col 11 in .w (e0).
// Ballots broadcast; bit (4*sub+2) of me = e0, bit (4*sub+1) of mc = cmp.

__global__ __launch_bounds__(256)
void gating_kernel(const float4* __restrict__ in,
                   float* __restrict__ out,
                   int n_tiles)          // tiles of 256 rows
{
    const unsigned FULL = 0xffffffffu;
    int lane = threadIdx.x & 31;
    int warp = threadIdx.x >> 5;

    // Hoisted per-lane store constants: store j writes output float
    // g_j = 32*j + lane of the warp's 96-float tile; row = g/3, col = g%3.
    int g0 = lane, g1 = lane + 32, g2 = lane + 64;
    int r0 = g0 / 3, r1 = g1 / 3, r2 = g2 / 3;
    int c0 = g0 - 3 * r0, c1 = g1 - 3 * r1, c2 = g2 - 3 * r2;
    int ch0 = r0 >> 3, ch1 = r1 >> 3, ch2 = r2 >> 3;
    int se0 = (r0 & 7) * 4, se1 = (r1 & 7) * 4, se2 = (r2 & 7) * 4;

    for (int ti = blockIdx.x; ti < n_tiles; ti += gridDim.x) {
        long long row_w = (long long)ti * 256 + warp * 32;   // warp's 32 rows
        const float4* src = in + row_w * 4;

        float4 v0 = src[lane];
        float4 v1 = src[lane + 32];
        float4 v2 = src[lane + 64];
        float4 v3 = src[lane + 96];

        unsigned m[8];
        m[0] = __ballot_sync(FULL, v0.w > 0.5f);
        m[1] = __ballot_sync(FULL, v0.x + v0.y > v0.z + v0.w);
        m[2] = __ballot_sync(FULL, v1.w > 0.5f);
        m[3] = __ballot_sync(FULL, v1.x + v1.y > v1.z + v1.w);
        m[4] = __ballot_sync(FULL, v2.w > 0.5f);
        m[5] = __ballot_sync(FULL, v2.x + v2.y > v2.z + v2.w);
        m[6] = __ballot_sync(FULL, v3.w > 0.5f);
        m[7] = __ballot_sync(FULL, v3.x + v3.y > v3.z + v3.w);

        auto val = [&](int ch, int se, int c) -> float {
            unsigned me = (ch & 2) ? ((ch & 1) ? m[6] : m[4])
                                   : ((ch & 1) ? m[2] : m[0]);
            unsigned mc = (ch & 2) ? ((ch & 1) ? m[7] : m[5])
                                   : ((ch & 1) ? m[3] : m[1]);
            bool e0 = (me >> (se + 2)) & 1;
            bool cm = (mc >> (se + 1)) & 1;
            int sel = e0 ? 0 : (cm ? 1 : 2);
            return (sel == c) ? 1.0f : 0.0f;
        };

        // 96 floats per warp; 3 stores, each a contiguous 128B warp span.
        float* dst = out + row_w * 3;
        __stcs(&dst[g0], val(ch0, se0, c0));
        __stcs(&dst[g1], val(ch1, se1, c1));
        __stcs(&dst[g2], val(ch2, se2, c2));
    }
}

extern "C" void kernel_launch(void* const* d_in, const int* in_sizes, int n_in,
                              void* d_out, int out_size)
{
    const float* features = (const float*)d_in[0];
    float* out = (float*)d_out;
    int n_rows = in_sizes[0] / 16;            // 4194304
    int n_tiles = n_rows / 256;               // 16384 (exact)

    // One wave: GB300 has 152 SMs; 8 CTAs/SM at 256 thr / 31 regs.
    // Grid-stride also covers 148-SM parts correctly.
    int grid = 152 * 8;                       // 1216
    gating_kernel<<<grid, 256>>>((const float4*)features, out, n_tiles);
}

// round 10
// speedup vs baseline: 1.0487x; 1.0487x over previous
#include <cuda_runtime.h>
#include <cuda_bf16.h>

// Rows = 4194304, 16 fp32/row (64B), out = rows x 3 fp32 one-hot.
// selected = (f11 > 0.5) ? 0 : ((f4+f5 > f6+f7) ? 1 : 2)
//
// Best shape (R8): fully-coalesced memcpy-style input stream, warp-ballot
// predicate exchange, all-lane scalar stores (3 x contiguous 128B warp
// spans), NITER=2, grid 8192. R9 (persistent) regressed -> reverted.
// Single change this round: __ldcs on loads (single-touch stream,
// evict-first keeps 256 MiB of dead lines from churning L2).

#define NITER 2    // 256 rows per block-iter -> 512 rows per block

__global__ __launch_bounds__(256)
void gating_kernel(const float4* __restrict__ in,
                   float* __restrict__ out,
                   int n_rows)
{
    const unsigned FULL = 0xffffffffu;
    int lane = threadIdx.x & 31;
    int warp = threadIdx.x >> 5;

    long long block_row0 = (long long)blockIdx.x * (256 * NITER);

    // Hoisted per-lane store constants: store j (j=0,1,2) writes output
    // float g_j = 32*j + lane of the warp's 96-float tile.
    int g0 = lane, g1 = lane + 32, g2 = lane + 64;
    int r0 = g0 / 3, r1 = g1 / 3, r2 = g2 / 3;
    int c0 = g0 - 3 * r0, c1 = g1 - 3 * r1, c2 = g2 - 3 * r2;
    int ch0 = r0 >> 3, ch1 = r1 >> 3, ch2 = r2 >> 3;
    int se0 = (r0 & 7) * 4, se1 = (r1 & 7) * 4, se2 = (r2 & 7) * 4;

#pragma unroll
    for (int it = 0; it < NITER; it++) {
        long long row_w = block_row0 + it * 256 + warp * 32;   // warp's 32 rows
        const float4* src = in + row_w * 4;

        // 4 contiguous LDG.128.CS per lane; 512B warp-contiguous each.
        float4 v0 = __ldcs(&src[lane]);
        float4 v1 = __ldcs(&src[lane + 32]);
        float4 v2 = __ldcs(&src[lane + 64]);
        float4 v3 = __ldcs(&src[lane + 96]);

        unsigned m[8];
        m[0] = __ballot_sync(FULL, v0.w > 0.5f);               // e0, chunk 0
        m[1] = __ballot_sync(FULL, v0.x + v0.y > v0.z + v0.w); // cmp, chunk 0
        m[2] = __ballot_sync(FULL, v1.w > 0.5f);
        m[3] = __ballot_sync(FULL, v1.x + v1.y > v1.z + v1.w);
        m[4] = __ballot_sync(FULL, v2.w > 0.5f);
        m[5] = __ballot_sync(FULL, v2.x + v2.y > v2.z + v2.w);
        m[6] = __ballot_sync(FULL, v3.w > 0.5f);
        m[7] = __ballot_sync(FULL, v3.x + v3.y > v3.z + v3.w);

        // Row r's predicates sit at bit (4*(r&7)+2) (e0) / +1 (cmp) of its
        // chunk's ballot masks.
        auto val = [&](int ch, int se, int c) -> float {
            unsigned me = (ch & 2) ? ((ch & 1) ? m[6] : m[4])
                                   : ((ch & 1) ? m[2] : m[0]);
            unsigned mc = (ch & 2) ? ((ch & 1) ? m[7] : m[5])
                                   : ((ch & 1) ? m[3] : m[1]);
            bool e0 = (me >> (se + 2)) & 1;
            bool cm = (mc >> (se + 1)) & 1;
            int sel = e0 ? 0 : (cm ? 1 : 2);
            return (sel == c) ? 1.0f : 0.0f;
        };

        // 96 floats per warp tile; 3 stores, each a contiguous 128B warp span.
        float* dst = out + row_w * 3;
        __stcs(&dst[g0], val(ch0, se0, c0));
        __stcs(&dst[g1], val(ch1, se1, c1));
        __stcs(&dst[g2], val(ch2, se2, c2));
    }
}

extern "C" void kernel_launch(void* const* d_in, const int* in_sizes, int n_in,
                              void* d_out, int out_size)
{
    const float* features = (const float*)d_in[0];
    float* out = (float*)d_out;
    int n_rows = in_sizes[0] / 16;                  // 4194304

    int rows_per_block = 256 * NITER;               // 512
    int grid = n_rows / rows_per_block;             // 8192 (exact)
    gating_kernel<<<grid, 256>>>((const float4*)features, out, n_rows);
}